// round 1
// baseline (speedup 1.0000x reference)
#include <cuda_runtime.h>
#include <cstdint>

#define KC 512
#define DD 64
#define NB 32
#define HW 4096
#define NVEC (NB * HW)          // 131072 vectors
#define NTH 256
#define NCHUNK (NVEC / NTH)     // 512 chunks of 256 vectors
#define GRID 148
#define SMEM_BYTES ((KC * DD + KC) * sizeof(float))  // 133120 B

// Packed fp32x2 FMA (sm_100+ PTX; ptxas never auto-fuses this from C++).
__device__ __forceinline__ unsigned long long ffma2(unsigned long long a,
                                                    unsigned long long b,
                                                    unsigned long long c) {
    unsigned long long d;
    asm("fma.rn.f32x2 %0, %1, %2, %3;" : "=l"(d) : "l"(a), "l"(b), "l"(c));
    return d;
}

__device__ __forceinline__ void unpack2(unsigned long long a, float& lo, float& hi) {
    asm("mov.b64 {%0, %1}, %2;" : "=f"(lo), "=f"(hi) : "l"(a));
}

__global__ void __launch_bounds__(NTH, 1)
vq_kernel(const float* __restrict__ ze, const float* __restrict__ cbg,
          float* __restrict__ out, int write2) {
    extern __shared__ float sm[];
    float* cb    = sm;             // [512][64]
    float* cbsqr = sm + KC * DD;   // [512]
    const int tid = threadIdx.x;

    // Stage codebook into smem (coalesced 128B loads).
    {
        const float4* g4 = (const float4*)cbg;
        float4*       s4 = (float4*)cb;
        #pragma unroll
        for (int i = tid; i < KC * DD / 4; i += NTH) s4[i] = g4[i];
    }
    __syncthreads();
    // ||c_k||^2 (value ~8e-5; rounding here is far below the distance
    // quantization granularity, so order doesn't matter).
    for (int k = tid; k < KC; k += NTH) {
        const float* row = cb + k * DD;
        float s = 0.f;
        #pragma unroll
        for (int d = 0; d < DD; d++) s = fmaf(row[d], row[d], s);
        cbsqr[k] = s;
    }
    __syncthreads();

    const unsigned long long* cbq = (const unsigned long long*)cb;  // f32x2 pairs

    // Persistent CTA: grid-stride over 512 chunks of 256 vectors.
    for (int chunk = blockIdx.x; chunk < NCHUNK; chunk += gridDim.x) {
        const int n = chunk * NTH + tid;       // flat NHWC vector index
        const int b = n >> 12;                 // n / 4096
        const int s = n & 4095;                // h*64 + w
        const float* xp = ze + (size_t)b * (DD * HW) + s;

        // Load x (strided d*HW, coalesced across the warp), pack into f32x2.
        unsigned long long x2[DD / 2];
        float xsqr = 0.f;
        #pragma unroll
        for (int j = 0; j < DD / 2; j++) {
            float lo = xp[(size_t)(2 * j) * HW];
            float hi = xp[(size_t)(2 * j + 1) * HW];
            xsqr = fmaf(lo, lo, xsqr);
            xsqr = fmaf(hi, hi, xsqr);
            asm("mov.b64 %0, {%1, %2};" : "=l"(x2[j]) : "f"(lo), "f"(hi));
        }

        float best  = 3.4028235e38f;
        int   bestk = 0;
        #pragma unroll 4   // body ~4KB: fits L0 I$, gives cross-k ILP
        for (int k = 0; k < KC; k++) {
            const unsigned long long* cr = cbq + k * (DD / 2);
            unsigned long long a0 = 0ull, a1 = 0ull, a2 = 0ull, a3 = 0ull;
            #pragma unroll
            for (int j = 0; j < 8; j++) {   // 32 packed FMAs, 4 indep chains
                a0 = ffma2(x2[4 * j + 0], cr[4 * j + 0], a0);
                a1 = ffma2(x2[4 * j + 1], cr[4 * j + 1], a1);
                a2 = ffma2(x2[4 * j + 2], cr[4 * j + 2], a2);
                a3 = ffma2(x2[4 * j + 3], cr[4 * j + 3], a3);
            }
            float f0, f1, f2, f3, f4, f5, f6, f7;
            unpack2(a0, f0, f1); unpack2(a1, f2, f3);
            unpack2(a2, f4, f5); unpack2(a3, f6, f7);
            float dot  = ((f0 + f1) + (f2 + f3)) + ((f4 + f5) + (f6 + f7));
            // Reference form: (cb_sqr + x_sqr) - 2*dot; 2*dot is exact, the
            // final subtract carries the same single rounding as the ref.
            float dist = (cbsqr[k] + xsqr) - 2.0f * dot;
            if (dist < best) { best = dist; bestk = k; }  // first-index tie-break
        }

        // Gather winning code from smem (float4 cuts bank-conflict replays 4x),
        // scatter to NCHW — coalesced across the warp for each d.
        const float4* code4 = (const float4*)(cb + bestk * DD);
        float* o1 = out + (size_t)b * (DD * HW) + s;
        float* o2 = o1 + (size_t)NVEC * DD;    // second tuple element
        #pragma unroll
        for (int q = 0; q < DD / 4; q++) {
            float4 v = code4[q];
            o1[(size_t)(4 * q + 0) * HW] = v.x;
            o1[(size_t)(4 * q + 1) * HW] = v.y;
            o1[(size_t)(4 * q + 2) * HW] = v.z;
            o1[(size_t)(4 * q + 3) * HW] = v.w;
            if (write2) {
                o2[(size_t)(4 * q + 0) * HW] = v.x;
                o2[(size_t)(4 * q + 1) * HW] = v.y;
                o2[(size_t)(4 * q + 2) * HW] = v.z;
                o2[(size_t)(4 * q + 3) * HW] = v.w;
            }
        }
    }
}

extern "C" void kernel_launch(void* const* d_in, const int* in_sizes, int n_in,
                              void* d_out, int out_size) {
    const float* ze  = (const float*)d_in[0];   // z_e_x [32,64,64,64] f32
    const float* cbg = (const float*)d_in[1];   // codebook [512,64] f32
    float* out = (float*)d_out;
    const int write2 = (out_size >= 2 * NVEC * DD) ? 1 : 0;
    // Idempotent, capture-safe (not a stream op, no allocation).
    cudaFuncSetAttribute(vq_kernel, cudaFuncAttributeMaxDynamicSharedMemorySize,
                         (int)SMEM_BYTES);
    vq_kernel<<<GRID, NTH, SMEM_BYTES>>>(ze, cbg, out, write2);
}

// round 2
// speedup vs baseline: 1.1627x; 1.1627x over previous
#include <cuda_runtime.h>
#include <cstdint>

#define KC 512
#define DD 64
#define NB 32
#define HW 4096
#define NVEC (NB * HW)              // 131072 vectors
#define NTH 256
#define NPT 2                       // vectors per thread
#define CHUNKN (NTH * NPT)          // 512 vectors per chunk
#define NCHUNK (NVEC / CHUNKN)      // 256 chunks
#define GRID 128                    // 2 chunks per CTA, perfectly balanced
#define SMEM_BYTES ((KC * DD + KC) * sizeof(float))  // 133120 B

// Packed fp32x2 FMA (sm_100+ PTX; ptxas never auto-fuses this from C++).
__device__ __forceinline__ unsigned long long ffma2(unsigned long long a,
                                                    unsigned long long b,
                                                    unsigned long long c) {
    unsigned long long d;
    asm("fma.rn.f32x2 %0, %1, %2, %3;" : "=l"(d) : "l"(a), "l"(b), "l"(c));
    return d;
}
__device__ __forceinline__ void unpack2(unsigned long long a, float& lo, float& hi) {
    asm("mov.b64 {%0, %1}, %2;" : "=f"(lo), "=f"(hi) : "l"(a));
}

__global__ void __launch_bounds__(NTH, 1)
vq_kernel(const float* __restrict__ ze, const float* __restrict__ cbg,
          float* __restrict__ out, int write2) {
    extern __shared__ float sm[];
    float* cb    = sm;             // [512][64]
    float* cbsqr = sm + KC * DD;   // [512]
    const int tid = threadIdx.x;

    // Stage codebook into smem (coalesced 128B loads).
    {
        const float4* g4 = (const float4*)cbg;
        float4*       s4 = (float4*)cb;
        #pragma unroll
        for (int i = tid; i < KC * DD / 4; i += NTH) s4[i] = g4[i];
    }
    __syncthreads();
    for (int k = tid; k < KC; k += NTH) {
        const float* row = cb + k * DD;
        float s = 0.f;
        #pragma unroll
        for (int d = 0; d < DD; d++) s = fmaf(row[d], row[d], s);
        cbsqr[k] = s;
    }
    __syncthreads();

    const unsigned long long* cbq = (const unsigned long long*)cb;  // f32x2 pairs

    for (int chunk = blockIdx.x; chunk < NCHUNK; chunk += gridDim.x) {
        // Two vectors per thread, 256 apart inside a 512-vector chunk.
        // 512 | 4096 so both share the same batch index b.
        const int n0 = chunk * CHUNKN + tid;
        const int b  = n0 >> 12;
        const int s0 = n0 & 4095;
        const float* xa = ze + (size_t)b * (DD * HW) + s0;
        const float* xb = xa + NTH;             // s0 + 256, same b

        unsigned long long x2a[DD / 2], x2b[DD / 2];
        float xsqra = 0.f, xsqrb = 0.f;
        #pragma unroll
        for (int j = 0; j < DD / 2; j++) {
            float la = xa[(size_t)(2 * j) * HW];
            float ha = xa[(size_t)(2 * j + 1) * HW];
            xsqra = fmaf(la, la, xsqra);
            xsqra = fmaf(ha, ha, xsqra);
            asm("mov.b64 %0, {%1, %2};" : "=l"(x2a[j]) : "f"(la), "f"(ha));
            float lb = xb[(size_t)(2 * j) * HW];
            float hb = xb[(size_t)(2 * j + 1) * HW];
            xsqrb = fmaf(lb, lb, xsqrb);
            xsqrb = fmaf(hb, hb, xsqrb);
            asm("mov.b64 %0, {%1, %2};" : "=l"(x2b[j]) : "f"(lb), "f"(hb));
        }

        float besta = 3.4028235e38f, bestb = 3.4028235e38f;
        int   bka = 0, bkb = 0;
        #pragma unroll 2
        for (int k = 0; k < KC; k++) {
            const unsigned long long* cr = cbq + k * (DD / 2);
            unsigned long long a0 = 0ull, a1 = 0ull, a2 = 0ull, a3 = 0ull;
            unsigned long long b0 = 0ull, b1 = 0ull, b2 = 0ull, b3 = 0ull;
            #pragma unroll
            for (int j = 0; j < 8; j++) {
                unsigned long long c0 = cr[4 * j + 0];
                unsigned long long c1 = cr[4 * j + 1];
                unsigned long long c2 = cr[4 * j + 2];
                unsigned long long c3 = cr[4 * j + 3];
                a0 = ffma2(x2a[4 * j + 0], c0, a0);
                b0 = ffma2(x2b[4 * j + 0], c0, b0);
                a1 = ffma2(x2a[4 * j + 1], c1, a1);
                b1 = ffma2(x2b[4 * j + 1], c1, b1);
                a2 = ffma2(x2a[4 * j + 2], c2, a2);
                b2 = ffma2(x2b[4 * j + 2], c2, b2);
                a3 = ffma2(x2a[4 * j + 3], c3, a3);
                b3 = ffma2(x2b[4 * j + 3], c3, b3);
            }
            // Reduction kept bit-identical to round 1 (rel_err was exactly 0).
            float f0, f1, f2, f3, f4, f5, f6, f7;
            unpack2(a0, f0, f1); unpack2(a1, f2, f3);
            unpack2(a2, f4, f5); unpack2(a3, f6, f7);
            float dota = ((f0 + f1) + (f2 + f3)) + ((f4 + f5) + (f6 + f7));
            float ck = cbsqr[k];
            float da = (ck + xsqra) - 2.0f * dota;
            if (da < besta) { besta = da; bka = k; }
            unpack2(b0, f0, f1); unpack2(b1, f2, f3);
            unpack2(b2, f4, f5); unpack2(b3, f6, f7);
            float dotb = ((f0 + f1) + (f2 + f3)) + ((f4 + f5) + (f6 + f7));
            float db = (ck + xsqrb) - 2.0f * dotb;
            if (db < bestb) { bestb = db; bkb = k; }
        }

        // Scatter winning codes (float4 smem gather, coalesced strided STG).
        #pragma unroll
        for (int v = 0; v < NPT; v++) {
            const int   kk = (v == 0) ? bka : bkb;
            const int   ss = s0 + v * NTH;
            const float4* code4 = (const float4*)(cb + kk * DD);
            float* o1 = out + (size_t)b * (DD * HW) + ss;
            float* o2 = o1 + (size_t)NVEC * DD;
            #pragma unroll
            for (int q = 0; q < DD / 4; q++) {
                float4 w = code4[q];
                o1[(size_t)(4 * q + 0) * HW] = w.x;
                o1[(size_t)(4 * q + 1) * HW] = w.y;
                o1[(size_t)(4 * q + 2) * HW] = w.z;
                o1[(size_t)(4 * q + 3) * HW] = w.w;
                if (write2) {
                    o2[(size_t)(4 * q + 0) * HW] = w.x;
                    o2[(size_t)(4 * q + 1) * HW] = w.y;
                    o2[(size_t)(4 * q + 2) * HW] = w.z;
                    o2[(size_t)(4 * q + 3) * HW] = w.w;
                }
            }
        }
    }
}

extern "C" void kernel_launch(void* const* d_in, const int* in_sizes, int n_in,
                              void* d_out, int out_size) {
    const float* ze  = (const float*)d_in[0];   // z_e_x [32,64,64,64] f32
    const float* cbg = (const float*)d_in[1];   // codebook [512,64] f32
    float* out = (float*)d_out;
    const int write2 = (out_size >= 2 * NVEC * DD) ? 1 : 0;
    cudaFuncSetAttribute(vq_kernel, cudaFuncAttributeMaxDynamicSharedMemorySize,
                         (int)SMEM_BYTES);
    vq_kernel<<<GRID, NTH, SMEM_BYTES>>>(ze, cbg, out, write2);
}

// round 3
// speedup vs baseline: 1.2816x; 1.1022x over previous
#include <cuda_runtime.h>
#include <cstdint>

#define KC 512
#define DD 64
#define NB 32
#define HW 4096
#define NVEC (NB * HW)              // 131072 vectors
#define NTH 256
#define NPT 2                       // vectors per thread
#define CHUNKN (NTH * NPT)          // 512 vectors per chunk
#define NCHUNK (NVEC / CHUNKN)      // 256 chunks
#define GRID 128                    // 2 chunks per CTA, perfectly balanced
#define SMEM_BYTES ((KC * DD + KC) * sizeof(float))  // 133120 B

typedef unsigned long long u64;

// Packed fp32x2 FMA (sm_100+ PTX; ptxas never auto-fuses this from C++).
__device__ __forceinline__ u64 ffma2(u64 a, u64 b, u64 c) {
    u64 d;
    asm("fma.rn.f32x2 %0, %1, %2, %3;" : "=l"(d) : "l"(a), "l"(b), "l"(c));
    return d;
}
__device__ __forceinline__ void unpack2(u64 a, float& lo, float& hi) {
    asm("mov.b64 {%0, %1}, %2;" : "=f"(lo), "=f"(hi) : "l"(a));
}

__global__ void __launch_bounds__(NTH, 1)
vq_kernel(const float* __restrict__ ze, const float* __restrict__ cbg,
          float* __restrict__ out, int write2) {
    extern __shared__ float sm[];
    float* cb    = sm;             // [512][64]
    float* cbsqr = sm + KC * DD;   // [512]
    const int tid = threadIdx.x;

    // Stage codebook into smem (coalesced 128B loads).
    {
        const float4* g4 = (const float4*)cbg;
        float4*       s4 = (float4*)cb;
        #pragma unroll
        for (int i = tid; i < KC * DD / 4; i += NTH) s4[i] = g4[i];
    }
    __syncthreads();
    for (int k = tid; k < KC; k += NTH) {
        const float* row = cb + k * DD;
        float s = 0.f;
        #pragma unroll
        for (int d = 0; d < DD; d++) s = fmaf(row[d], row[d], s);
        cbsqr[k] = s;
    }
    __syncthreads();

    const u64* cbq = (const u64*)cb;  // f32x2 pairs, 32 per row

    for (int chunk = blockIdx.x; chunk < NCHUNK; chunk += gridDim.x) {
        const int n0 = chunk * CHUNKN + tid;
        const int b  = n0 >> 12;
        const int s0 = n0 & 4095;
        const float* xa = ze + (size_t)b * (DD * HW) + s0;
        const float* xb = xa + NTH;             // s0 + 256, same b

        u64 x2a[DD / 2], x2b[DD / 2];
        float xsqra = 0.f, xsqrb = 0.f;
        #pragma unroll
        for (int j = 0; j < DD / 2; j++) {
            float la = xa[(size_t)(2 * j) * HW];
            float ha = xa[(size_t)(2 * j + 1) * HW];
            xsqra = fmaf(la, la, xsqra);
            xsqra = fmaf(ha, ha, xsqra);
            asm("mov.b64 %0, {%1, %2};" : "=l"(x2a[j]) : "f"(la), "f"(ha));
            float lb = xb[(size_t)(2 * j) * HW];
            float hb = xb[(size_t)(2 * j + 1) * HW];
            xsqrb = fmaf(lb, lb, xsqrb);
            xsqrb = fmaf(hb, hb, xsqrb);
            asm("mov.b64 %0, {%1, %2};" : "=l"(x2b[j]) : "f"(lb), "f"(hb));
        }

        float besta = 3.4028235e38f, bestb = 3.4028235e38f;
        int   bka = 0, bkb = 0;

        // Half-row double buffer: h0 = pairs 0..15 (j=0..3), h1 = pairs 16..31
        // (j=4..7). While FMAs consume one half, the other half's LDS batch is
        // in flight -> 29-cyc LDS latency stays off the critical path.
        u64 h0[16], h1[16];
        #pragma unroll
        for (int p = 0; p < 16; p++) h0[p] = cbq[p];   // k=0 first half

        #pragma unroll 2
        for (int k = 0; k < KC; k++) {
            const u64* cr  = cbq + k * 32;
            const u64* crn = cbq + ((k + 1) & (KC - 1)) * 32;

            // Prefetch second half of row k.
            #pragma unroll
            for (int p = 0; p < 16; p++) h1[p] = cr[16 + p];

            u64 a0 = 0ull, a1 = 0ull, a2 = 0ull, a3 = 0ull;
            u64 b0 = 0ull, b1 = 0ull, b2 = 0ull, b3 = 0ull;
            // FMAs on first half (j = 0..3) — covers the h1 LDS latency.
            #pragma unroll
            for (int j = 0; j < 4; j++) {
                u64 c0 = h0[4 * j + 0], c1 = h0[4 * j + 1];
                u64 c2 = h0[4 * j + 2], c3 = h0[4 * j + 3];
                a0 = ffma2(x2a[4 * j + 0], c0, a0);
                b0 = ffma2(x2b[4 * j + 0], c0, b0);
                a1 = ffma2(x2a[4 * j + 1], c1, a1);
                b1 = ffma2(x2b[4 * j + 1], c1, b1);
                a2 = ffma2(x2a[4 * j + 2], c2, a2);
                b2 = ffma2(x2b[4 * j + 2], c2, b2);
                a3 = ffma2(x2a[4 * j + 3], c3, a3);
                b3 = ffma2(x2b[4 * j + 3], c3, b3);
            }
            // Prefetch first half of row k+1.
            #pragma unroll
            for (int p = 0; p < 16; p++) h0[p] = crn[p];
            // FMAs on second half (j = 4..7) — covers the h0 LDS latency.
            #pragma unroll
            for (int j = 4; j < 8; j++) {
                u64 c0 = h1[4 * (j - 4) + 0], c1 = h1[4 * (j - 4) + 1];
                u64 c2 = h1[4 * (j - 4) + 2], c3 = h1[4 * (j - 4) + 3];
                a0 = ffma2(x2a[4 * j + 0], c0, a0);
                b0 = ffma2(x2b[4 * j + 0], c0, b0);
                a1 = ffma2(x2a[4 * j + 1], c1, a1);
                b1 = ffma2(x2b[4 * j + 1], c1, b1);
                a2 = ffma2(x2a[4 * j + 2], c2, a2);
                b2 = ffma2(x2b[4 * j + 2], c2, b2);
                a3 = ffma2(x2a[4 * j + 3], c3, a3);
                b3 = ffma2(x2b[4 * j + 3], c3, b3);
            }

            // Reduction kept bit-identical (rel_err has been exactly 0).
            float f0, f1, f2, f3, f4, f5, f6, f7;
            unpack2(a0, f0, f1); unpack2(a1, f2, f3);
            unpack2(a2, f4, f5); unpack2(a3, f6, f7);
            float dota = ((f0 + f1) + (f2 + f3)) + ((f4 + f5) + (f6 + f7));
            float ck = cbsqr[k];
            // fmaf(-2,dot,s) == (s - 2*dot): exact product, same single round.
            float da = fmaf(-2.0f, dota, ck + xsqra);
            if (da < besta) { besta = da; bka = k; }
            unpack2(b0, f0, f1); unpack2(b1, f2, f3);
            unpack2(b2, f4, f5); unpack2(b3, f6, f7);
            float dotb = ((f0 + f1) + (f2 + f3)) + ((f4 + f5) + (f6 + f7));
            float db = fmaf(-2.0f, dotb, ck + xsqrb);
            if (db < bestb) { bestb = db; bkb = k; }
        }

        // Scatter winning codes (float4 smem gather, coalesced strided STG).
        #pragma unroll
        for (int v = 0; v < NPT; v++) {
            const int   kk = (v == 0) ? bka : bkb;
            const int   ss = s0 + v * NTH;
            const float4* code4 = (const float4*)(cb + kk * DD);
            float* o1 = out + (size_t)b * (DD * HW) + ss;
            float* o2 = o1 + (size_t)NVEC * DD;
            #pragma unroll
            for (int q = 0; q < DD / 4; q++) {
                float4 w = code4[q];
                o1[(size_t)(4 * q + 0) * HW] = w.x;
                o1[(size_t)(4 * q + 1) * HW] = w.y;
                o1[(size_t)(4 * q + 2) * HW] = w.z;
                o1[(size_t)(4 * q + 3) * HW] = w.w;
                if (write2) {
                    o2[(size_t)(4 * q + 0) * HW] = w.x;
                    o2[(size_t)(4 * q + 1) * HW] = w.y;
                    o2[(size_t)(4 * q + 2) * HW] = w.z;
                    o2[(size_t)(4 * q + 3) * HW] = w.w;
                }
            }
        }
    }
}

extern "C" void kernel_launch(void* const* d_in, const int* in_sizes, int n_in,
                              void* d_out, int out_size) {
    const float* ze  = (const float*)d_in[0];   // z_e_x [32,64,64,64] f32
    const float* cbg = (const float*)d_in[1];   // codebook [512,64] f32
    float* out = (float*)d_out;
    const int write2 = (out_size >= 2 * NVEC * DD) ? 1 : 0;
    cudaFuncSetAttribute(vq_kernel, cudaFuncAttributeMaxDynamicSharedMemorySize,
                         (int)SMEM_BYTES);
    vq_kernel<<<GRID, NTH, SMEM_BYTES>>>(ze, cbg, out, write2);
}